// round 2
// baseline (speedup 1.0000x reference)
#include <cuda_runtime.h>
#include <math.h>

#define B 4
#define T 8192
#define C 1024
#define A 1024
#define H 16
#define D 64
#define NCHUNK 32
#define CH 256   // tokens per z chunk (T / NCHUNK)

// Scratch (static device globals; no allocation)
__device__ float g_q[B*A];
__device__ float g_u[B*H*C];
__device__ float g_scores[B*H*T];
__device__ float g_zpart[B*NCHUNK*H*C];
__device__ float g_z[B*H*C];

// ---------------------------------------------------------------------------
// K1: q[b,:] = Wq @ x[b, T-1, :] + bq       (one warp per output element)
// ---------------------------------------------------------------------------
__global__ void q_kernel(const float* __restrict__ x,
                         const float* __restrict__ Wq,
                         const float* __restrict__ bq) {
    int gw = blockIdx.x * 8 + (threadIdx.x >> 5);
    int lane = threadIdx.x & 31;
    int b = gw >> 10, a = gw & 1023;
    const float* xr = x + ((size_t)b * T + (T - 1)) * C;
    const float* wr = Wq + (size_t)a * C;
    float s = 0.f;
    #pragma unroll 8
    for (int c = lane; c < C; c += 32) s += wr[c] * xr[c];
    #pragma unroll
    for (int o = 16; o; o >>= 1) s += __shfl_down_sync(0xffffffffu, s, o);
    if (!lane) g_q[b * A + a] = s + bq[a];
}

// ---------------------------------------------------------------------------
// K2: u[b,h,:] = Wk_h^T @ q[b,h,:]   (bk dropped: constant per (b,h), cancels
// in softmax). One CTA per (b,h).
// ---------------------------------------------------------------------------
__global__ void u_kernel(const float* __restrict__ Wk) {
    int b = blockIdx.x >> 4, h = blockIdx.x & 15;
    __shared__ float qs[D];
    if (threadIdx.x < D) qs[threadIdx.x] = g_q[b * A + h * D + threadIdx.x];
    __syncthreads();
    for (int cc = threadIdx.x; cc < C; cc += 256) {
        float acc = 0.f;
        #pragma unroll 16
        for (int d = 0; d < D; d++)
            acc += qs[d] * Wk[(size_t)(h * D + d) * C + cc];
        g_u[(b * H + h) * C + cc] = acc;
    }
}

// ---------------------------------------------------------------------------
// K3: scores[b,h,t] = u[b,h,:] . x[b,t,:]
// CTA: 8 warps x 4 tokens = 32 tokens; u (64KB) in dynamic smem.
// Each warp registers-blocks 4 tokens so each u float4 LDS serves 16 FMA.
// ---------------------------------------------------------------------------
__global__ void scores_kernel(const float* __restrict__ x) {
    extern __shared__ float us[];           // H*C floats = 64KB
    int b  = blockIdx.x >> 8;               // 256 CTAs per batch
    int tb = blockIdx.x & 255;
    const float* ub = g_u + (size_t)b * H * C;
    for (int i = threadIdx.x; i < H * C; i += 256) us[i] = ub[i];
    __syncthreads();

    int warp = threadIdx.x >> 5, lane = threadIdx.x & 31;
    int t0 = (tb * 8 + warp) * 4;
    const float4* us4 = (const float4*)us;
    const float4* xr0 = (const float4*)(x + ((size_t)b * T + t0) * C);

    float acc[H][4];
    #pragma unroll
    for (int h = 0; h < H; h++)
        #pragma unroll
        for (int j = 0; j < 4; j++) acc[h][j] = 0.f;

    for (int i = lane; i < 256; i += 32) {
        float4 xv[4];
        #pragma unroll
        for (int j = 0; j < 4; j++) xv[j] = xr0[(size_t)j * 256 + i];
        #pragma unroll
        for (int h = 0; h < H; h++) {
            float4 u4 = us4[h * 256 + i];
            #pragma unroll
            for (int j = 0; j < 4; j++)
                acc[h][j] += u4.x * xv[j].x + u4.y * xv[j].y +
                             u4.z * xv[j].z + u4.w * xv[j].w;
        }
    }
    #pragma unroll
    for (int h = 0; h < H; h++)
        #pragma unroll
        for (int j = 0; j < 4; j++) {
            float v = acc[h][j];
            #pragma unroll
            for (int o = 16; o; o >>= 1) v += __shfl_down_sync(0xffffffffu, v, o);
            if (!lane) g_scores[((size_t)(b * H + h)) * T + t0 + j] = v;
        }
}

// ---------------------------------------------------------------------------
// K4: softmax over t for each (b,h); scale by 1/sqrt(D)=0.125 first.
// ---------------------------------------------------------------------------
__global__ void softmax_kernel() {
    float* s = g_scores + (size_t)blockIdx.x * T;
    __shared__ float red[256];
    int tid = threadIdx.x;

    float m = -1e30f;
    for (int i = tid; i < T; i += 256) m = fmaxf(m, s[i] * 0.125f);
    red[tid] = m; __syncthreads();
    for (int o = 128; o; o >>= 1) { if (tid < o) red[tid] = fmaxf(red[tid], red[tid + o]); __syncthreads(); }
    m = red[0]; __syncthreads();

    float sum = 0.f;
    for (int i = tid; i < T; i += 256) {
        float e = __expf(s[i] * 0.125f - m);
        s[i] = e;
        sum += e;
    }
    red[tid] = sum; __syncthreads();
    for (int o = 128; o; o >>= 1) { if (tid < o) red[tid] += red[tid + o]; __syncthreads(); }
    float inv = 1.f / red[0]; __syncthreads();

    for (int i = tid; i < T; i += 256) s[i] *= inv;
}

// ---------------------------------------------------------------------------
// K5: partial z: zpart[b,chunk,h,:] = sum_{t in chunk} attn[b,h,t] * x[b,t,:]
// CTA per (b,chunk); thread owns one float4 c-slice, 16 head accumulators.
// ---------------------------------------------------------------------------
__global__ void zpart_kernel(const float* __restrict__ x) {
    int b = blockIdx.x >> 5, chunk = blockIdx.x & 31;
    __shared__ float as[H * CH];
    int tid = threadIdx.x;
    for (int i = tid; i < H * CH; i += 256) {
        int h = i >> 8, t = i & (CH - 1);
        as[i] = g_scores[((size_t)(b * H + h)) * T + chunk * CH + t];
    }
    __syncthreads();

    float4 acc[H];
    #pragma unroll
    for (int h = 0; h < H; h++) acc[h] = make_float4(0.f, 0.f, 0.f, 0.f);

    const float4* xp = (const float4*)(x + ((size_t)b * T + (size_t)chunk * CH) * C);
    for (int t = 0; t < CH; t++) {
        float4 xv = xp[(size_t)t * 256 + tid];
        #pragma unroll
        for (int h = 0; h < H; h++) {
            float a = as[h * CH + t];
            acc[h].x += a * xv.x; acc[h].y += a * xv.y;
            acc[h].z += a * xv.z; acc[h].w += a * xv.w;
        }
    }
    float4* zp = (float4*)g_zpart;
    #pragma unroll
    for (int h = 0; h < H; h++)
        zp[(((size_t)(b * NCHUNK + chunk)) * H + h) * 256 + tid] = acc[h];
}

// ---------------------------------------------------------------------------
// K5b: z = sum over chunks of zpart (deterministic, fixed order)
// ---------------------------------------------------------------------------
__global__ void zreduce_kernel() {
    int idx = blockIdx.x * 256 + threadIdx.x;   // 0 .. B*H*C-1 = 65535
    int b = idx >> 14, r = idx & 16383;
    float s = 0.f;
    #pragma unroll 8
    for (int c = 0; c < NCHUNK; c++)
        s += g_zpart[((size_t)(b * NCHUNK + c)) * H * C + r];
    g_z[idx] = s;
}

// ---------------------------------------------------------------------------
// K6: y[b,a] = Wv[a,:] . z[b, a/64, :] + bv[a]   (one warp per output)
// ---------------------------------------------------------------------------
__global__ void y_kernel(const float* __restrict__ Wv,
                         const float* __restrict__ bv,
                         float* __restrict__ out) {
    int gw = blockIdx.x * 8 + (threadIdx.x >> 5);
    int lane = threadIdx.x & 31;
    int b = gw >> 10, a = gw & 1023;
    int h = a >> 6;
    const float* wr = Wv + (size_t)a * C;
    const float* zr = g_z + (size_t)(b * H + h) * C;
    float s = 0.f;
    #pragma unroll 8
    for (int c = lane; c < C; c += 32) s += wr[c] * zr[c];
    #pragma unroll
    for (int o = 16; o; o >>= 1) s += __shfl_down_sync(0xffffffffu, s, o);
    if (!lane) out[b * A + a] = s + bv[a];
}

// ---------------------------------------------------------------------------
extern "C" void kernel_launch(void* const* d_in, const int* in_sizes, int n_in,
                              void* d_out, int out_size) {
    const float* x  = (const float*)d_in[0];
    const float* Wk = (const float*)d_in[1];
    // const float* bk = (const float*)d_in[2];  // cancels in softmax
    const float* Wq = (const float*)d_in[3];
    const float* bq = (const float*)d_in[4];
    const float* Wv = (const float*)d_in[5];
    const float* bv = (const float*)d_in[6];
    float* out = (float*)d_out;

    static bool attr_done = false;
    if (!attr_done) {
        cudaFuncSetAttribute(scores_kernel,
                             cudaFuncAttributeMaxDynamicSharedMemorySize,
                             H * C * (int)sizeof(float));
        attr_done = true;
    }

    q_kernel<<<(B * A) / 8, 256>>>(x, Wq, bq);
    u_kernel<<<B * H, 256>>>(Wk);
    scores_kernel<<<B * 256, 256, H * C * sizeof(float)>>>(x);
    softmax_kernel<<<B * H, 256>>>();
    zpart_kernel<<<B * NCHUNK, 256>>>(x);
    zreduce_kernel<<<(B * H * C) / 256, 256>>>();
    y_kernel<<<(B * A) / 8, 256>>>(Wv, bv, out);
}

// round 3
// speedup vs baseline: 1.8241x; 1.8241x over previous
#include <cuda_runtime.h>
#include <math.h>

#define B 4
#define T 8192
#define C 1024
#define A 1024
#define H 16
#define D 64
#define NC 37              // chunks per batch
#define GRID (B*NC)        // 148 CTAs = one wave
#define SUB 16             // tokens per sub-tile

// ---------------- scratch (static device globals, no allocation) ----------
__device__ float g_q[B*A];
__device__ float g_u[B*H*C];
__device__ float g_state[GRID][2*H];   // [m(16), s(16)] per chunk
__device__ float g_zp[GRID][H][C];     // unnormalized exp-weighted partial z
__device__ float g_z[B*H*C];

// ---------------------------------------------------------------------------
// K1: q[b,:] = Wq @ x[b, T-1, :] + bq    (one warp per output element)
// ---------------------------------------------------------------------------
__global__ void q_kernel(const float* __restrict__ x,
                         const float* __restrict__ Wq,
                         const float* __restrict__ bq) {
    int gw = blockIdx.x * 8 + (threadIdx.x >> 5);
    int lane = threadIdx.x & 31;
    int b = gw >> 10, a = gw & 1023;
    const float* xr = x + ((size_t)b * T + (T - 1)) * C;
    const float* wr = Wq + (size_t)a * C;
    float s = 0.f;
    #pragma unroll 8
    for (int c = lane; c < C; c += 32) s += wr[c] * xr[c];
    #pragma unroll
    for (int o = 16; o; o >>= 1) s += __shfl_down_sync(0xffffffffu, s, o);
    if (!lane) g_q[b * A + a] = s + bq[a];
}

// ---------------------------------------------------------------------------
// K2: u[b,h,:] = Wk_h^T @ q[b,h,:]   (bk constant per (b,h) cancels in softmax)
// ---------------------------------------------------------------------------
__global__ void u_kernel(const float* __restrict__ Wk) {
    int b = blockIdx.x >> 4, h = blockIdx.x & 15;
    __shared__ float qs[D];
    if (threadIdx.x < D) qs[threadIdx.x] = g_q[b * A + h * D + threadIdx.x];
    __syncthreads();
    for (int cc = threadIdx.x; cc < C; cc += 256) {
        float acc = 0.f;
        #pragma unroll 16
        for (int d = 0; d < D; d++)
            acc += qs[d] * Wk[(size_t)(h * D + d) * C + cc];
        g_u[(b * H + h) * C + cc] = acc;
    }
}

// ---------------------------------------------------------------------------
// K3 (fused): single pass over x. Per-CTA chunk of ~221 tokens:
//   scores (u.x) -> online softmax state -> exp-weighted z accumulation.
// ---------------------------------------------------------------------------
struct __align__(16) FSmem {
    float us[H * C];          // 64 KB
    float xs[2][SUB * C];     // 128 KB double-buffered x tiles
    float sc[H][SUB];         // raw scores
    float wts[H][SUB];        // exp weights
    float rfac[H];            // rescale factors
    float mrun[H];
    float srun[H];
};

__device__ __forceinline__ void cp16(float* d, const float* s) {
    unsigned a = (unsigned)__cvta_generic_to_shared(d);
    asm volatile("cp.async.cg.shared.global [%0], [%1], 16;" :: "r"(a), "l"(s) : "memory");
}

__global__ __launch_bounds__(256, 1)
void fused_kernel(const float* __restrict__ x) {
    extern __shared__ char smraw[];
    FSmem& sm = *reinterpret_cast<FSmem*>(smraw);

    int tid = threadIdx.x;
    int blk = blockIdx.x;
    int b = blk / NC, c = blk % NC;
    int t0 = (c * T) / NC, t1 = ((c + 1) * T) / NC;
    int len = t1 - t0;
    int nsub = (len + SUB - 1) / SUB;

    // load u for this batch
    {
        const float4* src = (const float4*)(g_u + (size_t)b * H * C);
        float4* dst = (float4*)sm.us;
        #pragma unroll
        for (int i = 0; i < (H * C / 4) / 256; i++)
            dst[i * 256 + tid] = src[i * 256 + tid];
    }
    if (tid < H) { sm.mrun[tid] = -1e30f; sm.srun[tid] = 0.f; }

    const float* xbase = x + ((size_t)b * T + t0) * C;

    float4 zacc[H];
    #pragma unroll
    for (int h = 0; h < H; h++) zacc[h] = make_float4(0.f, 0.f, 0.f, 0.f);

    // prefetch tile 0
    {
        float* dstb = sm.xs[0];
        #pragma unroll
        for (int j = 0; j < SUB; j++) {
            if (j < len) cp16(dstb + j * C + tid * 4, xbase + (size_t)j * C + tid * 4);
            else *(float4*)(dstb + j * C + tid * 4) = make_float4(0.f, 0.f, 0.f, 0.f);
        }
        asm volatile("cp.async.commit_group;" ::: "memory");
    }

    int lane = tid & 31, warp = tid >> 5;
    int hb = (warp >> 2) * 8;   // head block base: 0 or 8
    int tb = (warp & 3) * 4;    // token block base: 0,4,8,12

    for (int k = 0; k < nsub; k++) {
        int buf = k & 1;
        if (k + 1 < nsub) {
            float* dstb = sm.xs[buf ^ 1];
            const float* g = xbase + (size_t)(k + 1) * SUB * C;
            int rem = len - (k + 1) * SUB;
            #pragma unroll
            for (int j = 0; j < SUB; j++) {
                if (j < rem) cp16(dstb + j * C + tid * 4, g + (size_t)j * C + tid * 4);
                else *(float4*)(dstb + j * C + tid * 4) = make_float4(0.f, 0.f, 0.f, 0.f);
            }
            asm volatile("cp.async.commit_group;" ::: "memory");
            asm volatile("cp.async.wait_group 1;" ::: "memory");
        } else {
            asm volatile("cp.async.wait_group 0;" ::: "memory");
        }
        __syncthreads();

        const float4* xb4 = (const float4*)sm.xs[buf];
        const float4* ub4 = (const float4*)sm.us;

        // ---- scores: warp computes 4 tokens x 8 heads ----
        float acc[4][8];
        #pragma unroll
        for (int j = 0; j < 4; j++)
            #pragma unroll
            for (int q = 0; q < 8; q++) acc[j][q] = 0.f;

        #pragma unroll
        for (int ii = 0; ii < 8; ii++) {
            int i = lane + ii * 32;
            float4 xv[4];
            #pragma unroll
            for (int j = 0; j < 4; j++) xv[j] = xb4[(tb + j) * (C / 4) + i];
            #pragma unroll
            for (int q = 0; q < 8; q++) {
                float4 u4 = ub4[(hb + q) * (C / 4) + i];
                #pragma unroll
                for (int j = 0; j < 4; j++)
                    acc[j][q] += u4.x * xv[j].x + u4.y * xv[j].y +
                                 u4.z * xv[j].z + u4.w * xv[j].w;
            }
        }
        #pragma unroll
        for (int off = 16; off; off >>= 1)
            #pragma unroll
            for (int j = 0; j < 4; j++)
                #pragma unroll
                for (int q = 0; q < 8; q++)
                    acc[j][q] += __shfl_xor_sync(0xffffffffu, acc[j][q], off);
        #pragma unroll
        for (int j = 0; j < 4; j++)
            #pragma unroll
            for (int q = 0; q < 8; q++)
                if (lane == j * 8 + q) sm.sc[hb + q][tb + j] = acc[j][q];
        __syncthreads();

        // ---- online softmax state update (16 threads, one per head) ----
        if (tid < H) {
            int h = tid;
            int vtok = len - k * SUB; if (vtok > SUB) vtok = SUB;
            float mold = sm.mrun[h];
            float mloc = -1e30f;
            for (int t = 0; t < vtok; t++) mloc = fmaxf(mloc, sm.sc[h][t] * 0.125f);
            float mnew = fmaxf(mold, mloc);
            float r = __expf(mold - mnew);
            float ssum = sm.srun[h] * r;
            #pragma unroll
            for (int t = 0; t < SUB; t++) {
                float w = (t < vtok) ? __expf(sm.sc[h][t] * 0.125f - mnew) : 0.f;
                sm.wts[h][t] = w;
                ssum += w;
            }
            sm.mrun[h] = mnew; sm.srun[h] = ssum; sm.rfac[h] = r;
        }
        __syncthreads();

        // ---- z accumulation: thread owns one float4 column slice ----
        float4 xv[SUB];
        #pragma unroll
        for (int t = 0; t < SUB; t++) xv[t] = xb4[t * (C / 4) + tid];
        #pragma unroll
        for (int h = 0; h < H; h++) {
            float r = sm.rfac[h];
            float4 z = zacc[h];
            z.x *= r; z.y *= r; z.z *= r; z.w *= r;
            const float4* wp = (const float4*)sm.wts[h];
            #pragma unroll
            for (int tq = 0; tq < 4; tq++) {
                float4 w4 = wp[tq];
                float4 x0 = xv[tq * 4 + 0], x1 = xv[tq * 4 + 1];
                float4 x2 = xv[tq * 4 + 2], x3 = xv[tq * 4 + 3];
                z.x += w4.x * x0.x + w4.y * x1.x + w4.z * x2.x + w4.w * x3.x;
                z.y += w4.x * x0.y + w4.y * x1.y + w4.z * x2.y + w4.w * x3.y;
                z.z += w4.x * x0.z + w4.y * x1.z + w4.z * x2.z + w4.w * x3.z;
                z.w += w4.x * x0.w + w4.y * x1.w + w4.z * x2.w + w4.w * x3.w;
            }
            zacc[h] = z;
        }
        __syncthreads();   // protect buf before next-next prefetch overwrites
    }

    // ---- epilogue: write chunk state + partial z ----
    if (tid < H) {
        g_state[blk][tid] = sm.mrun[tid];
        g_state[blk][H + tid] = sm.srun[tid];
    }
    float4* zp = (float4*)g_zp[blk];
    #pragma unroll
    for (int h = 0; h < H; h++) zp[h * (C / 4) + tid] = zacc[h];
}

// ---------------------------------------------------------------------------
// K4: combine chunk partials -> normalized z[b,h,:]
// ---------------------------------------------------------------------------
__global__ void combine_kernel() {
    int b = blockIdx.x >> 4, h = blockIdx.x & 15;
    __shared__ float f[NC];
    __shared__ float sinv;
    if (threadIdx.x == 0) {
        float mg = -1e30f;
        for (int c = 0; c < NC; c++) mg = fmaxf(mg, g_state[b * NC + c][h]);
        float S = 0.f;
        for (int c = 0; c < NC; c++) {
            float fc = __expf(g_state[b * NC + c][h] - mg);
            f[c] = fc;
            S += fc * g_state[b * NC + c][H + h];
        }
        sinv = 1.f / S;
    }
    __syncthreads();
    float inv = sinv;
    int tid = threadIdx.x;
    float4 z = make_float4(0.f, 0.f, 0.f, 0.f);
    for (int c = 0; c < NC; c++) {
        float fc = f[c];
        float4 v = ((const float4*)g_zp[b * NC + c][h])[tid];
        z.x += fc * v.x; z.y += fc * v.y; z.z += fc * v.z; z.w += fc * v.w;
    }
    ((float4*)(g_z + (size_t)(b * H + h) * C))[tid] =
        make_float4(z.x * inv, z.y * inv, z.z * inv, z.w * inv);
}

// ---------------------------------------------------------------------------
// K5: y[b,a] = Wv[a,:] . z[b, a/64, :] + bv[a]
// ---------------------------------------------------------------------------
__global__ void y_kernel(const float* __restrict__ Wv,
                         const float* __restrict__ bv,
                         float* __restrict__ out) {
    int gw = blockIdx.x * 8 + (threadIdx.x >> 5);
    int lane = threadIdx.x & 31;
    int b = gw >> 10, a = gw & 1023;
    int h = a >> 6;
    const float* wr = Wv + (size_t)a * C;
    const float* zr = g_z + (size_t)(b * H + h) * C;
    float s = 0.f;
    #pragma unroll 8
    for (int c = lane; c < C; c += 32) s += wr[c] * zr[c];
    #pragma unroll
    for (int o = 16; o; o >>= 1) s += __shfl_down_sync(0xffffffffu, s, o);
    if (!lane) out[b * A + a] = s + bv[a];
}

// ---------------------------------------------------------------------------
extern "C" void kernel_launch(void* const* d_in, const int* in_sizes, int n_in,
                              void* d_out, int out_size) {
    const float* x  = (const float*)d_in[0];
    const float* Wk = (const float*)d_in[1];
    // d_in[2] = bk: per-(b,h) constant, cancels in softmax
    const float* Wq = (const float*)d_in[3];
    const float* bq = (const float*)d_in[4];
    const float* Wv = (const float*)d_in[5];
    const float* bv = (const float*)d_in[6];
    float* out = (float*)d_out;

    cudaFuncSetAttribute(fused_kernel,
                         cudaFuncAttributeMaxDynamicSharedMemorySize,
                         (int)sizeof(FSmem));

    q_kernel<<<(B * A) / 8, 256>>>(x, Wq, bq);
    u_kernel<<<B * H, 256>>>(Wk);
    fused_kernel<<<GRID, 256, sizeof(FSmem)>>>(x);
    combine_kernel<<<B * H, 256>>>();
    y_kernel<<<(B * A) / 8, 256>>>(Wv, bv, out);
}

// round 4
// speedup vs baseline: 2.2563x; 1.2370x over previous
#include <cuda_runtime.h>
#include <math.h>

#define B 4
#define T 8192
#define C 1024
#define A 1024
#define H 16
#define D 64
#define NC 37              // chunks per batch
#define GRID (B*NC)        // 148 CTAs = one wave
#define SUB 16             // tokens per sub-tile

typedef unsigned long long u64;

// ---------------- scratch (static device globals, no allocation) ----------
__device__ float g_u[B*H*C];
__device__ float g_state[GRID][2*H];   // [m(16), s(16)] per chunk
__device__ float g_zp[GRID][H][C];     // unnormalized exp-weighted partial z
__device__ float g_z[B*H*C];

// ---------------- packed f32x2 helpers (sm_100a native) --------------------
__device__ __forceinline__ u64 fma2(u64 a, u64 b, u64 c) {
    u64 d;
    asm("fma.rn.f32x2 %0, %1, %2, %3;" : "=l"(d) : "l"(a), "l"(b), "l"(c));
    return d;
}
__device__ __forceinline__ u64 mul2(u64 a, u64 b) {
    u64 d;
    asm("mul.rn.f32x2 %0, %1, %2;" : "=l"(d) : "l"(a), "l"(b));
    return d;
}
__device__ __forceinline__ u64 pack2(float a, float b) {
    u64 r;
    asm("mov.b64 %0, {%1, %2};" : "=l"(r) : "f"(a), "f"(b));
    return r;
}
__device__ __forceinline__ float2 unpack2(u64 v) {
    float lo, hi;
    asm("mov.b64 {%0, %1}, %2;" : "=f"(lo), "=f"(hi) : "l"(v));
    return make_float2(lo, hi);
}

// ---------------------------------------------------------------------------
// K1 (fused q+u): per (b,h) CTA:
//   q_h[d] = Wq[h*64+d,:] . x[b,T-1,:] + bq   (8 warps x 8 d each)
//   u[b,h,cc] = sum_d q_h[d] * Wk[h*64+d, cc]
// bk dropped: per-(b,h) constant cancels in softmax.
// ---------------------------------------------------------------------------
__global__ void qu_kernel(const float* __restrict__ x,
                          const float* __restrict__ Wq,
                          const float* __restrict__ bq,
                          const float* __restrict__ Wk) {
    int b = blockIdx.x >> 4, h = blockIdx.x & 15;
    __shared__ float qs[D];
    int warp = threadIdx.x >> 5, lane = threadIdx.x & 31;
    const float4* xr = (const float4*)(x + ((size_t)b * T + (T - 1)) * C);

    #pragma unroll
    for (int dd = 0; dd < 8; dd++) {
        int d = warp * 8 + dd;
        const float4* wr = (const float4*)(Wq + (size_t)(h * D + d) * C);
        float s = 0.f;
        #pragma unroll 4
        for (int c = lane; c < C / 4; c += 32) {
            float4 w = wr[c], xv = xr[c];
            s += w.x * xv.x + w.y * xv.y + w.z * xv.z + w.w * xv.w;
        }
        #pragma unroll
        for (int o = 16; o; o >>= 1) s += __shfl_down_sync(0xffffffffu, s, o);
        if (!lane) qs[d] = s + bq[h * D + d];
    }
    __syncthreads();

    for (int cc = threadIdx.x; cc < C; cc += 256) {
        float acc = 0.f;
        #pragma unroll 16
        for (int d = 0; d < D; d++)
            acc += qs[d] * Wk[(size_t)(h * D + d) * C + cc];
        g_u[(b * H + h) * C + cc] = acc;
    }
}

// ---------------------------------------------------------------------------
// K2 (fused main): single pass over x with online softmax, f32x2 packed math.
// ---------------------------------------------------------------------------
struct __align__(16) FSmem {
    float us[H * C];          // 64 KB
    float xs[2][SUB * C];     // 128 KB double-buffered x tiles
    float sc[H][SUB];         // raw scores
    float wts[H][SUB];        // exp weights
    float rfac[H];            // rescale factors
    float mrun[H];
    float srun[H];
};

__device__ __forceinline__ void cp16(float* d, const float* s) {
    unsigned a = (unsigned)__cvta_generic_to_shared(d);
    asm volatile("cp.async.cg.shared.global [%0], [%1], 16;" :: "r"(a), "l"(s) : "memory");
}

__global__ __launch_bounds__(256, 1)
void fused_kernel(const float* __restrict__ x) {
    extern __shared__ char smraw[];
    FSmem& sm = *reinterpret_cast<FSmem*>(smraw);

    int tid = threadIdx.x;
    int blk = blockIdx.x;
    int b = blk / NC, c = blk % NC;
    int t0 = (c * T) / NC, t1 = ((c + 1) * T) / NC;
    int len = t1 - t0;
    int nsub = (len + SUB - 1) / SUB;

    // load u for this batch
    {
        const float4* src = (const float4*)(g_u + (size_t)b * H * C);
        float4* dst = (float4*)sm.us;
        #pragma unroll
        for (int i = 0; i < (H * C / 4) / 256; i++)
            dst[i * 256 + tid] = src[i * 256 + tid];
    }
    if (tid < H) { sm.mrun[tid] = -1e30f; sm.srun[tid] = 0.f; }

    const float* xbase = x + ((size_t)b * T + t0) * C;

    u64 zlo[H], zhi[H];
    #pragma unroll
    for (int h = 0; h < H; h++) { zlo[h] = 0ull; zhi[h] = 0ull; }

    // prefetch tile 0 (len >= 221 > SUB, so no guard needed)
    {
        float* dstb = sm.xs[0];
        #pragma unroll
        for (int j = 0; j < SUB; j++)
            cp16(dstb + j * C + tid * 4, xbase + (size_t)j * C + tid * 4);
        asm volatile("cp.async.commit_group;" ::: "memory");
    }

    int lane = tid & 31, warp = tid >> 5;
    int hb = (warp >> 2) * 8;   // head block base: 0 or 8
    int tb = (warp & 3) * 4;    // token block base: 0,4,8,12

    for (int k = 0; k < nsub; k++) {
        int buf = k & 1;
        if (k + 1 < nsub) {
            float* dstb = sm.xs[buf ^ 1];
            const float* g = xbase + (size_t)(k + 1) * SUB * C;
            int rem = len - (k + 1) * SUB;
            #pragma unroll
            for (int j = 0; j < SUB; j++) {
                if (j < rem) cp16(dstb + j * C + tid * 4, g + (size_t)j * C + tid * 4);
                else *(float4*)(dstb + j * C + tid * 4) = make_float4(0.f, 0.f, 0.f, 0.f);
            }
            asm volatile("cp.async.commit_group;" ::: "memory");
            asm volatile("cp.async.wait_group 1;" ::: "memory");
        } else {
            asm volatile("cp.async.wait_group 0;" ::: "memory");
        }
        __syncthreads();

        const ulonglong2* xb = (const ulonglong2*)sm.xs[buf];   // 256 entries/row
        const ulonglong2* ub = (const ulonglong2*)sm.us;

        // ---- scores: warp computes 4 tokens x 8 heads (packed f32x2) ----
        u64 acc2[4][8];
        #pragma unroll
        for (int j = 0; j < 4; j++)
            #pragma unroll
            for (int q = 0; q < 8; q++) acc2[j][q] = 0ull;

        #pragma unroll
        for (int ii = 0; ii < 8; ii++) {
            int i = lane + ii * 32;
            ulonglong2 xv[4];
            #pragma unroll
            for (int j = 0; j < 4; j++) xv[j] = xb[(tb + j) * 256 + i];
            #pragma unroll
            for (int q = 0; q < 8; q++) {
                ulonglong2 uv = ub[(hb + q) * 256 + i];
                #pragma unroll
                for (int j = 0; j < 4; j++) {
                    acc2[j][q] = fma2(uv.x, xv[j].x, acc2[j][q]);
                    acc2[j][q] = fma2(uv.y, xv[j].y, acc2[j][q]);
                }
            }
        }
        #pragma unroll
        for (int j = 0; j < 4; j++)
            #pragma unroll
            for (int q = 0; q < 8; q++) {
                float2 p = unpack2(acc2[j][q]);
                float v = p.x + p.y;
                #pragma unroll
                for (int o = 16; o; o >>= 1)
                    v += __shfl_xor_sync(0xffffffffu, v, o);
                if (lane == j * 8 + q) sm.sc[hb + q][tb + j] = v;
            }
        __syncthreads();

        // ---- online softmax state update (16 threads, one per head) ----
        if (tid < H) {
            int h = tid;
            int vtok = len - k * SUB; if (vtok > SUB) vtok = SUB;
            float mold = sm.mrun[h];
            float mloc = -1e30f;
            for (int t = 0; t < vtok; t++) mloc = fmaxf(mloc, sm.sc[h][t] * 0.125f);
            float mnew = fmaxf(mold, mloc);
            float r = __expf(mold - mnew);
            float ssum = sm.srun[h] * r;
            #pragma unroll
            for (int t = 0; t < SUB; t++) {
                float w = (t < vtok) ? __expf(sm.sc[h][t] * 0.125f - mnew) : 0.f;
                sm.wts[h][t] = w;
                ssum += w;
            }
            sm.mrun[h] = mnew; sm.srun[h] = ssum; sm.rfac[h] = r;
        }
        __syncthreads();

        // ---- z accumulation (packed): thread owns one float4 c-slice ----
        ulonglong2 xv[SUB];
        #pragma unroll
        for (int t = 0; t < SUB; t++) xv[t] = xb[t * 256 + tid];
        #pragma unroll
        for (int h = 0; h < H; h++) {
            float r = sm.rfac[h];
            u64 rr = pack2(r, r);
            u64 zl = mul2(zlo[h], rr);
            u64 zh = mul2(zhi[h], rr);
            const float4* wp = (const float4*)sm.wts[h];
            #pragma unroll
            for (int tq = 0; tq < 4; tq++) {
                float4 w4 = wp[tq];
                u64 w0 = pack2(w4.x, w4.x);
                u64 w1 = pack2(w4.y, w4.y);
                u64 w2 = pack2(w4.z, w4.z);
                u64 w3 = pack2(w4.w, w4.w);
                zl = fma2(w0, xv[tq * 4 + 0].x, zl);
                zh = fma2(w0, xv[tq * 4 + 0].y, zh);
                zl = fma2(w1, xv[tq * 4 + 1].x, zl);
                zh = fma2(w1, xv[tq * 4 + 1].y, zh);
                zl = fma2(w2, xv[tq * 4 + 2].x, zl);
                zh = fma2(w2, xv[tq * 4 + 2].y, zh);
                zl = fma2(w3, xv[tq * 4 + 3].x, zl);
                zh = fma2(w3, xv[tq * 4 + 3].y, zh);
            }
            zlo[h] = zl; zhi[h] = zh;
        }
        __syncthreads();   // protect buf before next prefetch overwrites it
    }

    // ---- epilogue: write chunk state + partial z ----
    if (tid < H) {
        g_state[blk][tid] = sm.mrun[tid];
        g_state[blk][H + tid] = sm.srun[tid];
    }
    float4* zp = (float4*)g_zp[blk];
    #pragma unroll
    for (int h = 0; h < H; h++) {
        float2 a = unpack2(zlo[h]), bb = unpack2(zhi[h]);
        zp[h * (C / 4) + tid] = make_float4(a.x, a.y, bb.x, bb.y);
    }
}

// ---------------------------------------------------------------------------
// K3: combine chunk partials -> normalized z[b,h,:]
// Parallel state staging into smem (fixes the serial global-latency scan).
// ---------------------------------------------------------------------------
__global__ void combine_kernel() {
    int b = blockIdx.x >> 4, h = blockIdx.x & 15;
    __shared__ float ms[NC], ss[NC], f[NC];
    __shared__ float sinv;
    int tid = threadIdx.x;
    if (tid < NC) {
        ms[tid] = g_state[b * NC + tid][h];
        ss[tid] = g_state[b * NC + tid][H + h];
    }
    __syncthreads();
    if (tid == 0) {
        float mg = -1e30f;
        #pragma unroll
        for (int c = 0; c < NC; c++) mg = fmaxf(mg, ms[c]);
        float S = 0.f;
        #pragma unroll
        for (int c = 0; c < NC; c++) {
            float fc = __expf(ms[c] - mg);
            f[c] = fc;
            S += fc * ss[c];
        }
        sinv = 1.f / S;
    }
    __syncthreads();
    float inv = sinv;

    float4 z0 = make_float4(0.f,0.f,0.f,0.f), z1 = z0, z2 = z0, z3 = z0;
    #pragma unroll
    for (int c = 0; c < NC; c += 4) {
        float4 v0 = ((const float4*)g_zp[b * NC + c][h])[tid];
        float f0 = f[c];
        z0.x += f0*v0.x; z0.y += f0*v0.y; z0.z += f0*v0.z; z0.w += f0*v0.w;
        if (c + 1 < NC) {
            float4 v1 = ((const float4*)g_zp[b * NC + c + 1][h])[tid];
            float f1 = f[c + 1];
            z1.x += f1*v1.x; z1.y += f1*v1.y; z1.z += f1*v1.z; z1.w += f1*v1.w;
        }
        if (c + 2 < NC) {
            float4 v2 = ((const float4*)g_zp[b * NC + c + 2][h])[tid];
            float f2 = f[c + 2];
            z2.x += f2*v2.x; z2.y += f2*v2.y; z2.z += f2*v2.z; z2.w += f2*v2.w;
        }
        if (c + 3 < NC) {
            float4 v3 = ((const float4*)g_zp[b * NC + c + 3][h])[tid];
            float f3 = f[c + 3];
            z3.x += f3*v3.x; z3.y += f3*v3.y; z3.z += f3*v3.z; z3.w += f3*v3.w;
        }
    }
    float4 z = make_float4((z0.x+z1.x)+(z2.x+z3.x), (z0.y+z1.y)+(z2.y+z3.y),
                           (z0.z+z1.z)+(z2.z+z3.z), (z0.w+z1.w)+(z2.w+z3.w));
    ((float4*)(g_z + (size_t)(b * H + h) * C))[tid] =
        make_float4(z.x * inv, z.y * inv, z.z * inv, z.w * inv);
}

// ---------------------------------------------------------------------------
// K4: y[b,a] = Wv[a,:] . z[b, a/64, :] + bv[a]
// ---------------------------------------------------------------------------
__global__ void y_kernel(const float* __restrict__ Wv,
                         const float* __restrict__ bv,
                         float* __restrict__ out) {
    int gw = blockIdx.x * 8 + (threadIdx.x >> 5);
    int lane = threadIdx.x & 31;
    int b = gw >> 10, a = gw & 1023;
    int h = a >> 6;
    const float4* wr = (const float4*)(Wv + (size_t)a * C);
    const float4* zr = (const float4*)(g_z + (size_t)(b * H + h) * C);
    float s = 0.f;
    #pragma unroll 4
    for (int c = lane; c < C / 4; c += 32) {
        float4 w = wr[c], zv = zr[c];
        s += w.x * zv.x + w.y * zv.y + w.z * zv.z + w.w * zv.w;
    }
    #pragma unroll
    for (int o = 16; o; o >>= 1) s += __shfl_down_sync(0xffffffffu, s, o);
    if (!lane) out[b * A + a] = s + bv[a];
}

// ---------------------------------------------------------------------------
extern "C" void kernel_launch(void* const* d_in, const int* in_sizes, int n_in,
                              void* d_out, int out_size) {
    const float* x  = (const float*)d_in[0];
    const float* Wk = (const float*)d_in[1];
    // d_in[2] = bk: per-(b,h) constant, cancels in softmax
    const float* Wq = (const float*)d_in[3];
    const float* bq = (const float*)d_in[4];
    const float* Wv = (const float*)d_in[5];
    const float* bv = (const float*)d_in[6];
    float* out = (float*)d_out;

    cudaFuncSetAttribute(fused_kernel,
                         cudaFuncAttributeMaxDynamicSharedMemorySize,
                         (int)sizeof(FSmem));

    qu_kernel<<<B * H, 256>>>(x, Wq, bq, Wk);
    fused_kernel<<<GRID, 256, sizeof(FSmem)>>>(x);
    combine_kernel<<<B * H, 256>>>();
    y_kernel<<<(B * A) / 8, 256>>>(Wv, bv, out);
}

// round 6
// speedup vs baseline: 2.8237x; 1.2515x over previous
#include <cuda_runtime.h>
#include <math.h>

#define B 4
#define T 8192
#define C 1024
#define A 1024
#define H 16
#define D 64
#define NC 37              // chunks per batch
#define GRID (B*NC)        // 148 CTAs = one wave
#define SUB 16             // tokens per sub-tile
#define PITCH 1028         // f32 x-tile row pitch (bank-stagger for frag loads)

typedef unsigned long long u64;
typedef unsigned int u32;

// ---------------- scratch (static device globals, no allocation) ----------
__device__ float g_u[B*H*C];
__device__ float g_state[GRID][2*H];   // [m(16), s(16)] per chunk
__device__ float g_zp[GRID][H][C];     // unnormalized exp-weighted partial z
__device__ float g_z[B*H*C];

// ---------------- packed f32x2 helpers -------------------------------------
__device__ __forceinline__ u64 fma2(u64 a, u64 b, u64 c) {
    u64 d;
    asm("fma.rn.f32x2 %0, %1, %2, %3;" : "=l"(d) : "l"(a), "l"(b), "l"(c));
    return d;
}
__device__ __forceinline__ u64 mul2(u64 a, u64 b) {
    u64 d;
    asm("mul.rn.f32x2 %0, %1, %2;" : "=l"(d) : "l"(a), "l"(b));
    return d;
}
__device__ __forceinline__ u64 pack2(float a, float b) {
    u64 r;
    asm("mov.b64 %0, {%1, %2};" : "=l"(r) : "f"(a), "f"(b));
    return r;
}
__device__ __forceinline__ float2 unpack2(u64 v) {
    float lo, hi;
    asm("mov.b64 {%0, %1}, %2;" : "=f"(lo), "=f"(hi) : "l"(v));
    return make_float2(lo, hi);
}

// ---------------- bf16x3 split: (x0,x1) -> hi bf16x2, lo bf16x2 ------------
__device__ __forceinline__ void split2(float x0, float x1, u32& hi, u32& lo) {
    u32 h;
    asm("cvt.rn.bf16x2.f32 %0, %1, %2;" : "=r"(h) : "f"(x1), "f"(x0));
    float h0 = __uint_as_float(h << 16);
    float h1 = __uint_as_float(h & 0xffff0000u);
    float l0 = x0 - h0, l1 = x1 - h1;
    u32 l;
    asm("cvt.rn.bf16x2.f32 %0, %1, %2;" : "=r"(l) : "f"(l1), "f"(l0));
    hi = h; lo = l;
}

// ---------------- mma.sync m16n8k16 bf16, D += A*B -------------------------
__device__ __forceinline__ void mma16816(float* d, const u32* a, const u32* bb) {
    asm volatile(
        "mma.sync.aligned.m16n8k16.row.col.f32.bf16.bf16.f32 "
        "{%0,%1,%2,%3}, {%4,%5,%6,%7}, {%8,%9}, {%0,%1,%2,%3};"
        : "+f"(d[0]), "+f"(d[1]), "+f"(d[2]), "+f"(d[3])
        : "r"(a[0]), "r"(a[1]), "r"(a[2]), "r"(a[3]), "r"(bb[0]), "r"(bb[1]));
}

// ---------------------------------------------------------------------------
// K1 (fused q+u): per (b,h) CTA: q then u = Wk_h^T q. bk cancels in softmax.
// ---------------------------------------------------------------------------
__global__ void qu_kernel(const float* __restrict__ x,
                          const float* __restrict__ Wq,
                          const float* __restrict__ bq,
                          const float* __restrict__ Wk) {
    int b = blockIdx.x >> 4, h = blockIdx.x & 15;
    __shared__ float qs[D];
    int warp = threadIdx.x >> 5, lane = threadIdx.x & 31;
    const float4* xr = (const float4*)(x + ((size_t)b * T + (T - 1)) * C);

    #pragma unroll
    for (int dd = 0; dd < 8; dd++) {
        int d = warp * 8 + dd;
        const float4* wr = (const float4*)(Wq + (size_t)(h * D + d) * C);
        float s = 0.f;
        #pragma unroll 4
        for (int c = lane; c < C / 4; c += 32) {
            float4 w = wr[c], xv = xr[c];
            s += w.x * xv.x + w.y * xv.y + w.z * xv.z + w.w * xv.w;
        }
        #pragma unroll
        for (int o = 16; o; o >>= 1) s += __shfl_down_sync(0xffffffffu, s, o);
        if (!lane) qs[d] = s + bq[h * D + d];
    }
    __syncthreads();

    for (int cc = threadIdx.x; cc < C; cc += 256) {
        float acc = 0.f;
        #pragma unroll 16
        for (int d = 0; d < D; d++)
            acc += qs[d] * Wk[(size_t)(h * D + d) * C + cc];
        g_u[(b * H + h) * C + cc] = acc;
    }
}

// ---------------------------------------------------------------------------
// K2 (fused main): single pass over x. Scores via tensor-core mma (bf16x3
// split, u-fragments register-resident per warp), online softmax, packed-f32
// z accumulation.
// ---------------------------------------------------------------------------
struct __align__(16) FSmem {
    float xs[2][SUB * PITCH];   // 131584 B double-buffered f32 x tiles
    float spart[8][SUB][18];    // per-warp score partials (padded)
    u64   wts2[H][SUB];         // duplicated exp weights (w,w)
    float rfac[H];
    float mrun[H];
    float srun[H];
};

__device__ __forceinline__ void cp16(float* d, const float* s) {
    unsigned a = (unsigned)__cvta_generic_to_shared(d);
    asm volatile("cp.async.cg.shared.global [%0], [%1], 16;" :: "r"(a), "l"(s) : "memory");
}

__global__ __launch_bounds__(256, 1)
void fused_kernel(const float* __restrict__ x) {
    extern __shared__ char smraw[];
    FSmem& sm = *reinterpret_cast<FSmem*>(smraw);

    int tid = threadIdx.x;
    int lane = tid & 31, warp = tid >> 5;
    int blk = blockIdx.x;
    int b = blk / NC, c = blk % NC;
    int t0 = (c * T) / NC, t1 = ((c + 1) * T) / NC;
    int len = t1 - t0;
    int nsub = (len + SUB - 1) / SUB;

    // ---- load this warp's u B-fragments into registers (hi/lo split) ----
    // Warp w owns k-slice [w*128, (w+1)*128): 8 k-steps of 16. nt: heads 0-7 / 8-15.
    u32 ubh[8][2][2], ubl[8][2][2];
    {
        int hq = lane >> 2, c2 = (lane & 3) * 2;
        #pragma unroll
        for (int kk = 0; kk < 8; kk++)
            #pragma unroll
            for (int nt = 0; nt < 2; nt++) {
                const float* up = g_u + ((size_t)(b * H) + nt * 8 + hq) * C
                                  + warp * 128 + kk * 16 + c2;
                float2 p0 = *(const float2*)(up);
                float2 p1 = *(const float2*)(up + 8);
                split2(p0.x, p0.y, ubh[kk][nt][0], ubl[kk][nt][0]);
                split2(p1.x, p1.y, ubh[kk][nt][1], ubl[kk][nt][1]);
            }
    }

    if (tid < H) { sm.mrun[tid] = -1e30f; sm.srun[tid] = 0.f; }

    const float* xbase = x + ((size_t)b * T + t0) * C;

    u64 zlo[H], zhi[H];
    #pragma unroll
    for (int h = 0; h < H; h++) { zlo[h] = 0ull; zhi[h] = 0ull; }

    // prefetch tile 0 (len >= 221 > SUB, no guard)
    {
        float* dstb = sm.xs[0];
        #pragma unroll
        for (int j = 0; j < SUB; j++)
            cp16(dstb + j * PITCH + tid * 4, xbase + (size_t)j * C + tid * 4);
        asm volatile("cp.async.commit_group;" ::: "memory");
    }

    int r  = lane >> 2;          // fragment row (token)
    int c2 = (lane & 3) * 2;     // fragment col pair

    for (int k = 0; k < nsub; k++) {
        int buf = k & 1;
        if (k + 1 < nsub) {
            float* dstb = sm.xs[buf ^ 1];
            const float* g = xbase + (size_t)(k + 1) * SUB * C;
            int rem = len - (k + 1) * SUB;
            #pragma unroll
            for (int j = 0; j < SUB; j++) {
                if (j < rem) cp16(dstb + j * PITCH + tid * 4, g + (size_t)j * C + tid * 4);
                else *(float4*)(dstb + j * PITCH + tid * 4) = make_float4(0.f, 0.f, 0.f, 0.f);
            }
            asm volatile("cp.async.commit_group;" ::: "memory");
            asm volatile("cp.async.wait_group 1;" ::: "memory");
        } else {
            asm volatile("cp.async.wait_group 0;" ::: "memory");
        }
        __syncthreads();   // (A) x[buf] ready

        const float* xb = sm.xs[buf];

        // ---- scores via tensor cores: warp's k-slice partial of S[16,16] ----
        {
            float d0[4] = {0.f, 0.f, 0.f, 0.f};
            float d1[4] = {0.f, 0.f, 0.f, 0.f};
            #pragma unroll
            for (int kk = 0; kk < 8; kk++) {
                int cb = warp * 128 + kk * 16 + c2;
                float2 x0 = *(const float2*)(xb + r * PITCH + cb);
                float2 x1 = *(const float2*)(xb + (r + 8) * PITCH + cb);
                float2 x2 = *(const float2*)(xb + r * PITCH + cb + 8);
                float2 x3 = *(const float2*)(xb + (r + 8) * PITCH + cb + 8);
                u32 ah[4], al[4];
                split2(x0.x, x0.y, ah[0], al[0]);
                split2(x1.x, x1.y, ah[1], al[1]);
                split2(x2.x, x2.y, ah[2], al[2]);
                split2(x3.x, x3.y, ah[3], al[3]);
                // hi*hi + lo*hi + hi*lo  (lo*lo negligible)
                mma16816(d0, ah, ubh[kk][0]);
                mma16816(d0, al, ubh[kk][0]);
                mma16816(d0, ah, ubl[kk][0]);
                mma16816(d1, ah, ubh[kk][1]);
                mma16816(d1, al, ubh[kk][1]);
                mma16816(d1, ah, ubl[kk][1]);
            }
            *(float2*)&sm.spart[warp][r][c2]         = make_float2(d0[0], d0[1]);
            *(float2*)&sm.spart[warp][r + 8][c2]     = make_float2(d0[2], d0[3]);
            *(float2*)&sm.spart[warp][r][8 + c2]     = make_float2(d1[0], d1[1]);
            *(float2*)&sm.spart[warp][r + 8][8 + c2] = make_float2(d1[2], d1[3]);
        }
        __syncthreads();   // (B) spart complete

        // ---- combine partials + online softmax (warp w: heads 2w, 2w+1) ----
        {
            int hh = 2 * warp + (lane >> 4);
            int t = lane & 15;
            int vtok = len - k * SUB; if (vtok > SUB) vtok = SUB;
            float s = 0.f;
            #pragma unroll
            for (int w = 0; w < 8; w++) s += sm.spart[w][t][hh];
            s *= 0.125f;
            float mloc = (t < vtok) ? s : -1e30f;
            #pragma unroll
            for (int o = 1; o < 16; o <<= 1)
                mloc = fmaxf(mloc, __shfl_xor_sync(0xffffffffu, mloc, o));
            float mold = sm.mrun[hh];
            float mnew = fmaxf(mold, mloc);
            float wgt = (t < vtok) ? __expf(s - mnew) : 0.f;
            sm.wts2[hh][t] = pack2(wgt, wgt);
            float ssum = wgt;
            #pragma unroll
            for (int o = 1; o < 16; o <<= 1)
                ssum += __shfl_xor_sync(0xffffffffu, ssum, o);
            if (t == 0) {
                float rr = __expf(mold - mnew);
                sm.rfac[hh] = rr;
                sm.mrun[hh] = mnew;
                sm.srun[hh] = sm.srun[hh] * rr + ssum;
            }
        }
        __syncthreads();   // (C) weights ready

        // ---- z accumulation (packed): thread owns one float4 c-slice ----
        {
            ulonglong2 xv[SUB];
            #pragma unroll
            for (int t = 0; t < SUB; t++)
                xv[t] = *(const ulonglong2*)(xb + t * PITCH + tid * 4);
            #pragma unroll
            for (int h = 0; h < H; h++) {
                float rr = sm.rfac[h];
                u64 rp = pack2(rr, rr);
                u64 zl = mul2(zlo[h], rp);
                u64 zh = mul2(zhi[h], rp);
                const ulonglong2* wp = (const ulonglong2*)sm.wts2[h];
                #pragma unroll
                for (int tq = 0; tq < 4; tq++) {
                    ulonglong2 wa = wp[tq * 2], wb = wp[tq * 2 + 1];
                    zl = fma2(wa.x, xv[tq * 4 + 0].x, zl);
                    zh = fma2(wa.x, xv[tq * 4 + 0].y, zh);
                    zl = fma2(wa.y, xv[tq * 4 + 1].x, zl);
                    zh = fma2(wa.y, xv[tq * 4 + 1].y, zh);
                    zl = fma2(wb.x, xv[tq * 4 + 2].x, zl);
                    zh = fma2(wb.x, xv[tq * 4 + 2].y, zh);
                    zl = fma2(wb.y, xv[tq * 4 + 3].x, zl);
                    zh = fma2(wb.y, xv[tq * 4 + 3].y, zh);
                }
                zlo[h] = zl; zhi[h] = zh;
            }
        }
        __syncthreads();   // (D) z done; next prefetch may overwrite buf
    }

    // ---- epilogue: write chunk state + partial z ----
    if (tid < H) {
        g_state[blk][tid] = sm.mrun[tid];
        g_state[blk][H + tid] = sm.srun[tid];
    }
    float4* zp = (float4*)g_zp[blk];
    #pragma unroll
    for (int h = 0; h < H; h++) {
        float2 a = unpack2(zlo[h]), bb = unpack2(zhi[h]);
        zp[h * (C / 4) + tid] = make_float4(a.x, a.y, bb.x, bb.y);
    }
}

// ---------------------------------------------------------------------------
// K3: combine chunk partials -> normalized z[b,h,:]
// Warp 0 computes m/S in parallel (shfl reductions over NC entries).
// ---------------------------------------------------------------------------
__global__ void combine_kernel() {
    int b = blockIdx.x >> 4, h = blockIdx.x & 15;
    __shared__ float f[NC];
    __shared__ float sinv;
    int tid = threadIdx.x;
    int lane = tid & 31;

    if (tid < 32) {
        // two NC-wide strips per lane (NC=37 <= 64)
        float m0 = (lane < NC) ? g_state[b * NC + lane][h] : -1e30f;
        float m1 = (lane + 32 < NC) ? g_state[b * NC + lane + 32][h] : -1e30f;
        float s0 = (lane < NC) ? g_state[b * NC + lane][H + h] : 0.f;
        float s1 = (lane + 32 < NC) ? g_state[b * NC + lane + 32][H + h] : 0.f;
        float mg = fmaxf(m0, m1);
        #pragma unroll
        for (int o = 16; o; o >>= 1)
            mg = fmaxf(mg, __shfl_xor_sync(0xffffffffu, mg, o));
        float f0 = __expf(m0 - mg), f1 = __expf(m1 - mg);
        if (lane < NC) f[lane] = f0;
        if (lane + 32 < NC) f[lane + 32] = f1;
        float S = f0 * s0 + f1 * s1;
        #pragma unroll
        for (int o = 16; o; o >>= 1)
            S += __shfl_xor_sync(0xffffffffu, S, o);
        if (!lane) sinv = 1.f / S;
    }
    __syncthreads();
    float inv = sinv;

    float4 z0 = make_float4(0.f,0.f,0.f,0.f), z1 = z0, z2 = z0, z3 = z0;
    #pragma unroll
    for (int c = 0; c < NC; c += 4) {
        float4 v0 = ((const float4*)g_zp[b * NC + c][h])[tid];
        float f0 = f[c];
        z0.x += f0*v0.x; z0.y += f0*v0.y; z0.z += f0*v0.z; z0.w += f0*v0.w;
        if (c + 1 < NC) {
            float4 v1 = ((const float4*)g_zp[b * NC + c + 1][h])[tid];
            float f1 = f[c + 1];
            z1.x += f1*v1.x; z1.y += f1*v1.y; z1.z += f1*v1.z; z1.w += f1*v1.w;
        }
        if (c + 2 < NC) {
            float4 v2 = ((const float4*)g_zp[b * NC + c + 2][h])[tid];
            float f2 = f[c + 2];
            z2.x += f2*v2.x; z2.y += f2*v2.y; z2.z += f2*v2.z; z2.w += f2*v2.w;
        }
        if (c + 3 < NC) {
            float4 v3 = ((const float4*)g_zp[b * NC + c + 3][h])[tid];
            float f3 = f[c + 3];
            z3.x += f3*v3.x; z3.y += f3*v3.y; z3.z += f3*v3.z; z3.w += f3*v3.w;
        }
    }
    float4 z = make_float4((z0.x+z1.x)+(z2.x+z3.x), (z0.y+z1.y)+(z2.y+z3.y),
                           (z0.z+z1.z)+(z2.z+z3.z), (z0.w+z1.w)+(z2.w+z3.w));
    ((float4*)(g_z + (size_t)(b * H + h) * C))[tid] =
        make_float4(z.x * inv, z.y * inv, z.z * inv, z.w * inv);
}

// ---------------------------------------------------------------------------
// K4: y[b,a] = Wv[a,:] . z[b, a/64, :] + bv[a]
// One warp per a-row computes ALL 4 batches (Wv read once).
// ---------------------------------------------------------------------------
__global__ void y_kernel(const float* __restrict__ Wv,
                         const float* __restrict__ bv,
                         float* __restrict__ out) {
    int a = blockIdx.x * 8 + (threadIdx.x >> 5);
    int lane = threadIdx.x & 31;
    int h = a >> 6;
    const float4* wr = (const float4*)(Wv + (size_t)a * C);
    const float4* z0 = (const float4*)(g_z + (size_t)(0 * H + h) * C);
    const float4* z1 = (const float4*)(g_z + (size_t)(1 * H + h) * C);
    const float4* z2 = (const float4*)(g_z + (size_t)(2 * H + h) * C);
    const float4* z3 = (const float4*)(g_z + (size_t)(3 * H + h) * C);
    float s0 = 0.f, s1 = 0.f, s2 = 0.f, s3 = 0.f;
    #pragma unroll 4
    for (int c = lane; c < C / 4; c += 32) {
        float4 w = wr[c];
        float4 v0 = z0[c], v1 = z1[c], v2 = z2[c], v3 = z3[c];
        s0 += w.x*v0.x + w.y*v0.y + w.z*v0.z + w.w*v0.w;
        s1 += w.x*v1.x + w.y*v1.y + w.z*v1.z + w.w*v1.w;
        s2 += w.x*v2.x + w.y*v2.y + w.z*v2.z + w.w*v2.w;
        s3 += w.x*v3.x + w.y*v3.y + w.z*v3.z + w.w*v3.w;
    }
    #pragma unroll
    for (int o = 16; o; o >>= 1) {
        s0 += __shfl_down_sync(0xffffffffu, s0, o);
        s1 += __shfl_down_sync(0xffffffffu, s1, o);
        s2 += __shfl_down_sync(0xffffffffu, s2, o);
        s3 += __shfl_down_sync(0xffffffffu, s3, o);
    }
    if (!lane) {
        float bvv = bv[a];
        out[0 * A + a] = s0 + bvv;
        out[1 * A + a] = s1 + bvv;
        out[2 * A + a] = s2 + bvv;
        out[3 * A + a] = s3 + bvv;
    }
}

// ---------------------------------------------------------------------------
extern "C" void kernel_launch(void* const* d_in, const int* in_sizes, int n_in,
                              void* d_out, int out_size) {
    const float* x  = (const float*)d_in[0];
    const float* Wk = (const float*)d_in[1];
    // d_in[2] = bk: per-(b,h) constant, cancels in softmax
    const float* Wq = (const float*)d_in[3];
    const float* bq = (const float*)d_in[4];
    const float* Wv = (const float*)d_in[5];
    const float* bv = (const float*)d_in[6];
    float* out = (float*)d_out;

    cudaFuncSetAttribute(fused_kernel,
                         cudaFuncAttributeMaxDynamicSharedMemorySize,
                         (int)sizeof(FSmem));

    qu_kernel<<<B * H, 256>>>(x, Wq, bq, Wk);
    fused_kernel<<<GRID, 256, sizeof(FSmem)>>>(x);
    combine_kernel<<<B * H, 256>>>();
    y_kernel<<<A / 8, 256>>>(Wv, bv, out);
}

// round 7
// speedup vs baseline: 3.1080x; 1.1007x over previous
#include <cuda_runtime.h>
#include <math.h>

#define B 4
#define T 8192
#define C 1024
#define A 1024
#define H 16
#define D 64
#define NC 37              // chunks per batch
#define GRID (B*NC)        // 148 CTAs = one wave
#define SUB 16             // tokens per sub-tile
#define PITCH 1028         // f32 x-tile row pitch (bank-stagger for frag loads)

typedef unsigned long long u64;
typedef unsigned int u32;

// ---------------- scratch (static device globals, no allocation) ----------
__device__ float g_q[B*A];
__device__ float g_u[B*H*C];           // pre-scaled by 0.125
__device__ float g_state[GRID][2*H];   // [m(16), s(16)] per chunk
__device__ float g_zp[GRID][H][C];     // unnormalized exp-weighted partial z
__device__ float g_z[B*H*C];

// ---------------- packed f32x2 helpers -------------------------------------
__device__ __forceinline__ u64 fma2(u64 a, u64 b, u64 c) {
    u64 d;
    asm("fma.rn.f32x2 %0, %1, %2, %3;" : "=l"(d) : "l"(a), "l"(b), "l"(c));
    return d;
}
__device__ __forceinline__ u64 mul2(u64 a, u64 b) {
    u64 d;
    asm("mul.rn.f32x2 %0, %1, %2;" : "=l"(d) : "l"(a), "l"(b));
    return d;
}
__device__ __forceinline__ u64 pack2(float a, float b) {
    u64 r;
    asm("mov.b64 %0, {%1, %2};" : "=l"(r) : "f"(a), "f"(b));
    return r;
}
__device__ __forceinline__ float2 unpack2(u64 v) {
    float lo, hi;
    asm("mov.b64 {%0, %1}, %2;" : "=f"(lo), "=f"(hi) : "l"(v));
    return make_float2(lo, hi);
}

// ---------------- bf16x3 split: (x0,x1) -> hi bf16x2, lo bf16x2 ------------
__device__ __forceinline__ void split2(float x0, float x1, u32& hi, u32& lo) {
    u32 h;
    asm("cvt.rn.bf16x2.f32 %0, %1, %2;" : "=r"(h) : "f"(x1), "f"(x0));
    float h0 = __uint_as_float(h << 16);
    float h1 = __uint_as_float(h & 0xffff0000u);
    float l0 = x0 - h0, l1 = x1 - h1;
    u32 l;
    asm("cvt.rn.bf16x2.f32 %0, %1, %2;" : "=r"(l) : "f"(l1), "f"(l0));
    hi = h; lo = l;
}

// ---------------- mma.sync m16n8k16 bf16, D += A*B -------------------------
__device__ __forceinline__ void mma16816(float* d, const u32* a, const u32* bb) {
    asm volatile(
        "mma.sync.aligned.m16n8k16.row.col.f32.bf16.bf16.f32 "
        "{%0,%1,%2,%3}, {%4,%5,%6,%7}, {%8,%9}, {%0,%1,%2,%3};"
        : "+f"(d[0]), "+f"(d[1]), "+f"(d[2]), "+f"(d[3])
        : "r"(a[0]), "r"(a[1]), "r"(a[2]), "r"(a[3]), "r"(bb[0]), "r"(bb[1]));
}

// ---------------------------------------------------------------------------
// K0: q[b,a] = Wq[a,:] . x[b,T-1,:] + bq[a]    (warp per (b,a); grid 512)
// ---------------------------------------------------------------------------
__global__ void q_kernel(const float* __restrict__ x,
                         const float* __restrict__ Wq,
                         const float* __restrict__ bq) {
    int gw = blockIdx.x * 8 + (threadIdx.x >> 5);
    int lane = threadIdx.x & 31;
    int b = gw >> 10, a = gw & 1023;
    const float4* xr = (const float4*)(x + ((size_t)b * T + (T - 1)) * C);
    const float4* wr = (const float4*)(Wq + (size_t)a * C);
    float s = 0.f;
    #pragma unroll 8
    for (int c = lane; c < C / 4; c += 32) {
        float4 w = wr[c], xv = xr[c];
        s += w.x * xv.x + w.y * xv.y + w.z * xv.z + w.w * xv.w;
    }
    #pragma unroll
    for (int o = 16; o; o >>= 1) s += __shfl_down_sync(0xffffffffu, s, o);
    if (!lane) g_q[b * A + a] = s + bq[a];
}

// ---------------------------------------------------------------------------
// K1: u[b,h,col] = 0.125 * sum_d q[b,h,d] * Wk[h*64+d, col]
// Grid = H x 8 col-slices; each CTA computes ALL 4 batches (Wk read once).
// ---------------------------------------------------------------------------
__global__ void u_kernel(const float* __restrict__ Wk) {
    int h = blockIdx.x >> 3, cs = blockIdx.x & 7;
    __shared__ float qs[B][D];
    int tid = threadIdx.x;   // 128 threads
    #pragma unroll
    for (int i = tid; i < B * D; i += 128) {
        int b = i >> 6, d = i & 63;
        qs[b][d] = g_q[b * A + h * D + d];
    }
    __syncthreads();
    int col = cs * 128 + tid;
    float a0 = 0.f, a1 = 0.f, a2 = 0.f, a3 = 0.f;
    const float* wp = Wk + (size_t)(h * D) * C + col;
    #pragma unroll 8
    for (int d = 0; d < D; d++) {
        float w = wp[(size_t)d * C];
        a0 += qs[0][d] * w;
        a1 += qs[1][d] * w;
        a2 += qs[2][d] * w;
        a3 += qs[3][d] * w;
    }
    g_u[(0 * H + h) * C + col] = a0 * 0.125f;
    g_u[(1 * H + h) * C + col] = a1 * 0.125f;
    g_u[(2 * H + h) * C + col] = a2 * 0.125f;
    g_u[(3 * H + h) * C + col] = a3 * 0.125f;
}

// ---------------------------------------------------------------------------
// K2 (fused main): single pass over x. Scores via tensor-core mma (bf16x3
// split, u-fragments register-resident), online softmax, packed-f32 z accum.
// Triple-buffered x tiles: no tail barrier needed.
// ---------------------------------------------------------------------------
struct __align__(16) FSmem {
    float xs[3][SUB * PITCH];   // 197376 B triple-buffered f32 x tiles
    float spart[8][SUB][18];    // per-warp score partials (padded)
    u64   wts2[H][SUB];         // duplicated exp weights (w,w)
    float rfac[H];
    float mrun[H];
    float srun[H];
};

__device__ __forceinline__ void cp16(float* d, const float* s) {
    unsigned a = (unsigned)__cvta_generic_to_shared(d);
    asm volatile("cp.async.cg.shared.global [%0], [%1], 16;" :: "r"(a), "l"(s) : "memory");
}

__global__ __launch_bounds__(256, 1)
void fused_kernel(const float* __restrict__ x) {
    extern __shared__ char smraw[];
    FSmem& sm = *reinterpret_cast<FSmem*>(smraw);

    int tid = threadIdx.x;
    int lane = tid & 31, warp = tid >> 5;
    int blk = blockIdx.x;
    int b = blk / NC, c = blk % NC;
    int t0 = (c * T) / NC, t1 = ((c + 1) * T) / NC;
    int len = t1 - t0;
    int nsub = (len + SUB - 1) / SUB;

    // ---- load this warp's u B-fragments into registers (hi/lo split) ----
    u32 ubh[8][2][2], ubl[8][2][2];
    {
        int hq = lane >> 2, cc2 = (lane & 3) * 2;
        #pragma unroll
        for (int kk = 0; kk < 8; kk++)
            #pragma unroll
            for (int nt = 0; nt < 2; nt++) {
                const float* up = g_u + ((size_t)(b * H) + nt * 8 + hq) * C
                                  + warp * 128 + kk * 16 + cc2;
                float2 p0 = *(const float2*)(up);
                float2 p1 = *(const float2*)(up + 8);
                split2(p0.x, p0.y, ubh[kk][nt][0], ubl[kk][nt][0]);
                split2(p1.x, p1.y, ubh[kk][nt][1], ubl[kk][nt][1]);
            }
    }

    if (tid < H) { sm.mrun[tid] = -1e30f; sm.srun[tid] = 0.f; }

    const float* xbase = x + ((size_t)b * T + t0) * C;

    u64 zlo[H], zhi[H];
    #pragma unroll
    for (int h = 0; h < H; h++) { zlo[h] = 0ull; zhi[h] = 0ull; }

    // prefetch tiles 0 and 1 (len >= 221 > 2*SUB, both full)
    #pragma unroll
    for (int p = 0; p < 2; p++) {
        float* dstb = sm.xs[p];
        #pragma unroll
        for (int j = 0; j < SUB; j++)
            cp16(dstb + j * PITCH + tid * 4, xbase + (size_t)(p * SUB + j) * C + tid * 4);
        asm volatile("cp.async.commit_group;" ::: "memory");
    }

    int r   = lane >> 2;         // fragment row (token)
    int cc2 = (lane & 3) * 2;    // fragment col pair

    for (int k = 0; k < nsub; k++) {
        int buf = k % 3;
        asm volatile("cp.async.wait_group 1;" ::: "memory");
        __syncthreads();   // (A) x[buf] ready; all threads done z of k-1

        // issue prefetch k+2 into xs[(k+2)%3] (z of k-1 already complete)
        if (k + 2 < nsub) {
            float* dstb = sm.xs[(k + 2) % 3];
            const float* g = xbase + (size_t)(k + 2) * SUB * C;
            int rem = len - (k + 2) * SUB;
            #pragma unroll
            for (int j = 0; j < SUB; j++) {
                if (j < rem) cp16(dstb + j * PITCH + tid * 4, g + (size_t)j * C + tid * 4);
                else *(float4*)(dstb + j * PITCH + tid * 4) = make_float4(0.f, 0.f, 0.f, 0.f);
            }
        }
        asm volatile("cp.async.commit_group;" ::: "memory");

        const float* xb = sm.xs[buf];

        // ---- scores via tensor cores: warp's k-slice partial of S[16,16] ----
        {
            float d0[4] = {0.f, 0.f, 0.f, 0.f};
            float d1[4] = {0.f, 0.f, 0.f, 0.f};
            #pragma unroll
            for (int kk = 0; kk < 8; kk++) {
                int cb = warp * 128 + kk * 16 + cc2;
                float2 x0 = *(const float2*)(xb + r * PITCH + cb);
                float2 x1 = *(const float2*)(xb + (r + 8) * PITCH + cb);
                float2 x2 = *(const float2*)(xb + r * PITCH + cb + 8);
                float2 x3 = *(const float2*)(xb + (r + 8) * PITCH + cb + 8);
                u32 ah[4], al[4];
                split2(x0.x, x0.y, ah[0], al[0]);
                split2(x1.x, x1.y, ah[1], al[1]);
                split2(x2.x, x2.y, ah[2], al[2]);
                split2(x3.x, x3.y, ah[3], al[3]);
                // hi*hi + lo*hi + hi*lo  (lo*lo negligible)
                mma16816(d0, ah, ubh[kk][0]);
                mma16816(d0, al, ubh[kk][0]);
                mma16816(d0, ah, ubl[kk][0]);
                mma16816(d1, ah, ubh[kk][1]);
                mma16816(d1, al, ubh[kk][1]);
                mma16816(d1, ah, ubl[kk][1]);
            }
            *(float2*)&sm.spart[warp][r][cc2]         = make_float2(d0[0], d0[1]);
            *(float2*)&sm.spart[warp][r + 8][cc2]     = make_float2(d0[2], d0[3]);
            *(float2*)&sm.spart[warp][r][8 + cc2]     = make_float2(d1[0], d1[1]);
            *(float2*)&sm.spart[warp][r + 8][8 + cc2] = make_float2(d1[2], d1[3]);
        }
        __syncthreads();   // (B) spart complete

        // ---- combine partials + online softmax (warp w: heads 2w, 2w+1) ----
        {
            int hh = 2 * warp + (lane >> 4);
            int t = lane & 15;
            int vtok = len - k * SUB; if (vtok > SUB) vtok = SUB;
            float s = 0.f;
            #pragma unroll
            for (int w = 0; w < 8; w++) s += sm.spart[w][t][hh];
            // u pre-scaled by 0.125
            float mloc = (t < vtok) ? s : -1e30f;
            #pragma unroll
            for (int o = 1; o < 16; o <<= 1)
                mloc = fmaxf(mloc, __shfl_xor_sync(0xffffffffu, mloc, o));
            float mold = sm.mrun[hh];
            float mnew = fmaxf(mold, mloc);
            float wgt = (t < vtok) ? __expf(s - mnew) : 0.f;
            sm.wts2[hh][t] = pack2(wgt, wgt);
            float ssum = wgt;
            #pragma unroll
            for (int o = 1; o < 16; o <<= 1)
                ssum += __shfl_xor_sync(0xffffffffu, ssum, o);
            if (t == 0) {
                float rr = __expf(mold - mnew);
                sm.rfac[hh] = rr;
                sm.mrun[hh] = mnew;
                sm.srun[hh] = sm.srun[hh] * rr + ssum;
            }
        }
        __syncthreads();   // (C) weights ready

        // ---- z accumulation (packed): thread owns one float4 c-slice ----
        {
            ulonglong2 xv[SUB];
            #pragma unroll
            for (int t = 0; t < SUB; t++)
                xv[t] = *(const ulonglong2*)(xb + t * PITCH + tid * 4);
            #pragma unroll
            for (int h = 0; h < H; h++) {
                float rr = sm.rfac[h];
                u64 rp = pack2(rr, rr);
                u64 zl = mul2(zlo[h], rp);
                u64 zh = mul2(zhi[h], rp);
                const ulonglong2* wp = (const ulonglong2*)sm.wts2[h];
                #pragma unroll
                for (int tq = 0; tq < 4; tq++) {
                    ulonglong2 wa = wp[tq * 2], wb = wp[tq * 2 + 1];
                    zl = fma2(wa.x, xv[tq * 4 + 0].x, zl);
                    zh = fma2(wa.x, xv[tq * 4 + 0].y, zh);
                    zl = fma2(wa.y, xv[tq * 4 + 1].x, zl);
                    zh = fma2(wa.y, xv[tq * 4 + 1].y, zh);
                    zl = fma2(wb.x, xv[tq * 4 + 2].x, zl);
                    zh = fma2(wb.x, xv[tq * 4 + 2].y, zh);
                    zl = fma2(wb.y, xv[tq * 4 + 3].x, zl);
                    zh = fma2(wb.y, xv[tq * 4 + 3].y, zh);
                }
                zlo[h] = zl; zhi[h] = zh;
            }
        }
        // no tail barrier: next iteration's (A) barrier protects xs[(k+2)%3]
    }

    // ---- epilogue: write chunk state + partial z ----
    if (tid < H) {
        g_state[blk][tid] = sm.mrun[tid];
        g_state[blk][H + tid] = sm.srun[tid];
    }
    float4* zp = (float4*)g_zp[blk];
    #pragma unroll
    for (int h = 0; h < H; h++) {
        float2 a = unpack2(zlo[h]), bb = unpack2(zhi[h]);
        zp[h * (C / 4) + tid] = make_float4(a.x, a.y, bb.x, bb.y);
    }
}

// ---------------------------------------------------------------------------
// K3: combine chunk partials -> normalized z[b,h,:]
// ---------------------------------------------------------------------------
__global__ void combine_kernel() {
    int b = blockIdx.x >> 4, h = blockIdx.x & 15;
    __shared__ float f[NC];
    __shared__ float sinv;
    int tid = threadIdx.x;
    int lane = tid & 31;

    if (tid < 32) {
        float m0 = (lane < NC) ? g_state[b * NC + lane][h] : -1e30f;
        float m1 = (lane + 32 < NC) ? g_state[b * NC + lane + 32][h] : -1e30f;
        float s0 = (lane < NC) ? g_state[b * NC + lane][H + h] : 0.f;
        float s1 = (lane + 32 < NC) ? g_state[b * NC + lane + 32][H + h] : 0.f;
        float mg = fmaxf(m0, m1);
        #pragma unroll
        for (int o = 16; o; o >>= 1)
            mg = fmaxf(mg, __shfl_xor_sync(0xffffffffu, mg, o));
        float f0 = __expf(m0 - mg), f1 = __expf(m1 - mg);
        if (lane < NC) f[lane] = f0;
        if (lane + 32 < NC) f[lane + 32] = f1;
        float S = f0 * s0 + f1 * s1;
        #pragma unroll
        for (int o = 16; o; o >>= 1)
            S += __shfl_xor_sync(0xffffffffu, S, o);
        if (!lane) sinv = 1.f / S;
    }
    __syncthreads();
    float inv = sinv;

    float4 z0 = make_float4(0.f,0.f,0.f,0.f), z1 = z0, z2 = z0, z3 = z0;
    #pragma unroll
    for (int c = 0; c < NC; c += 4) {
        float4 v0 = ((const float4*)g_zp[b * NC + c][h])[tid];
        float f0 = f[c];
        z0.x += f0*v0.x; z0.y += f0*v0.y; z0.z += f0*v0.z; z0.w += f0*v0.w;
        if (c + 1 < NC) {
            float4 v1 = ((const float4*)g_zp[b * NC + c + 1][h])[tid];
            float f1 = f[c + 1];
            z1.x += f1*v1.x; z1.y += f1*v1.y; z1.z += f1*v1.z; z1.w += f1*v1.w;
        }
        if (c + 2 < NC) {
            float4 v2 = ((const float4*)g_zp[b * NC + c + 2][h])[tid];
            float f2 = f[c + 2];
            z2.x += f2*v2.x; z2.y += f2*v2.y; z2.z += f2*v2.z; z2.w += f2*v2.w;
        }
        if (c + 3 < NC) {
            float4 v3 = ((const float4*)g_zp[b * NC + c + 3][h])[tid];
            float f3 = f[c + 3];
            z3.x += f3*v3.x; z3.y += f3*v3.y; z3.z += f3*v3.z; z3.w += f3*v3.w;
        }
    }
    float4 z = make_float4((z0.x+z1.x)+(z2.x+z3.x), (z0.y+z1.y)+(z2.y+z3.y),
                           (z0.z+z1.z)+(z2.z+z3.z), (z0.w+z1.w)+(z2.w+z3.w));
    ((float4*)(g_z + (size_t)(b * H + h) * C))[tid] =
        make_float4(z.x * inv, z.y * inv, z.z * inv, z.w * inv);
}

// ---------------------------------------------------------------------------
// K4: y[b,a] = Wv[a,:] . z[b, a/64, :] + bv[a]   (warp per (b,a); grid 512)
// ---------------------------------------------------------------------------
__global__ void y_kernel(const float* __restrict__ Wv,
                         const float* __restrict__ bv,
                         float* __restrict__ out) {
    int gw = blockIdx.x * 8 + (threadIdx.x >> 5);
    int lane = threadIdx.x & 31;
    int b = gw >> 10, a = gw & 1023;
    int h = a >> 6;
    const float4* wr = (const float4*)(Wv + (size_t)a * C);
    const float4* zr = (const float4*)(g_z + (size_t)(b * H + h) * C);
    float s = 0.f;
    #pragma unroll 8
    for (int c = lane; c < C / 4; c += 32) {
        float4 w = wr[c], zv = zr[c];
        s += w.x * zv.x + w.y * zv.y + w.z * zv.z + w.w * zv.w;
    }
    #pragma unroll
    for (int o = 16; o; o >>= 1) s += __shfl_down_sync(0xffffffffu, s, o);
    if (!lane) out[b * A + a] = s + bv[a];
}

// ---------------------------------------------------------------------------
extern "C" void kernel_launch(void* const* d_in, const int* in_sizes, int n_in,
                              void* d_out, int out_size) {
    const float* x  = (const float*)d_in[0];
    const float* Wk = (const float*)d_in[1];
    // d_in[2] = bk: per-(b,h) constant, cancels in softmax
    const float* Wq = (const float*)d_in[3];
    const float* bq = (const float*)d_in[4];
    const float* Wv = (const float*)d_in[5];
    const float* bv = (const float*)d_in[6];
    float* out = (float*)d_out;

    cudaFuncSetAttribute(fused_kernel,
                         cudaFuncAttributeMaxDynamicSharedMemorySize,
                         (int)sizeof(FSmem));

    q_kernel<<<(B * A) / 8, 256>>>(x, Wq, bq);
    u_kernel<<<H * 8, 128>>>(Wk);
    fused_kernel<<<GRID, 256, sizeof(FSmem)>>>(x);
    combine_kernel<<<B * H, 256>>>();
    y_kernel<<<(B * A) / 8, 256>>>(Wv, bv, out);
}